// round 4
// baseline (speedup 1.0000x reference)
#include <cuda_runtime.h>
#include <cuda_fp16.h>

// Problem constants
#define FX 80
#define NX 128
#define HH 512
#define WW 1024
#define BC 16                 // B*C fused channel count
#define M  (FX * NX * NX)     // 1310720 texels per channel
#define HW (HH * WW)          // 524288 pixels

// Scratch: x transposed + converted to fp16, layout [M][16] halfs (32B/texel).
__device__ __align__(128) __half g_xt[(size_t)M * BC];

__device__ __forceinline__ unsigned int h2u(__half2 h) {
    return *reinterpret_cast<unsigned int*>(&h);
}

// ---------------------------------------------------------------------------
// Pass 1: fused transpose+convert, register-only, float4-wide.
// Thread handles 4 consecutive texels: 16 coalesced LDG.128 (one per channel,
// 512B per warp per channel), then per-texel convert to 8 half2 and write
// 4 x 32B = 128B contiguous via 8 STG.128. No smem, no barriers.
// ---------------------------------------------------------------------------
__global__ void __launch_bounds__(256) transpose_kernel(const float* __restrict__ x) {
    const int t0 = (blockIdx.x * 256 + threadIdx.x) * 4;   // first of 4 texels

    float4 v[16];
#pragma unroll
    for (int c = 0; c < 16; c++)
        v[c] = *reinterpret_cast<const float4*>(x + (size_t)c * M + t0);

    uint4* dst = reinterpret_cast<uint4*>(g_xt + (size_t)t0 * BC);
#pragma unroll
    for (int i = 0; i < 4; i++) {
        const float* vf = reinterpret_cast<const float*>(v);   // vf[c*4 + i]
        unsigned int w[8];
#pragma unroll
        for (int j = 0; j < 8; j++)
            w[j] = h2u(__floats2half2_rn(vf[(2 * j) * 4 + i], vf[(2 * j + 1) * 4 + i]));
        dst[2 * i]     = make_uint4(w[0], w[1], w[2], w[3]);
        dst[2 * i + 1] = make_uint4(w[4], w[5], w[6], w[7]);
    }
}

// accumulate 8 fp16 channels (one uint4) into fp32 accumulators with weight w
__device__ __forceinline__ void acc8(float* r, const uint4& a, float w) {
    const __half2* h = reinterpret_cast<const __half2*>(&a);
#pragma unroll
    for (int j = 0; j < 4; j++) {
        float2 f = __half22float2(h[j]);
        r[2 * j]     = fmaf(f.x, w, r[2 * j]);
        r[2 * j + 1] = fmaf(f.y, w, r[2 * j + 1]);
    }
}

// ---------------------------------------------------------------------------
// Pass 2: bilinear gather. Block = 256 threads = 128 pixels x 2 half-groups.
// Each thread: 4 independent LDG.128 (16B = 8 fp16 channels per corner).
// Direct stores, no smem/barrier: warp covers 16 consecutive pixels, so each
// channel-plane store is a fully-used 64B segment per warp.
// ---------------------------------------------------------------------------
__global__ void __launch_bounds__(256) sample_kernel(const int*   __restrict__ quad,
                                                     const float* __restrict__ uv,
                                                     float*       __restrict__ out) {
    const int t   = threadIdx.x;
    const int p   = t >> 1;            // pixel-in-tile 0..127
    const int hg  = t & 1;             // half-group: channels hg*8 .. hg*8+7
    const int pix = blockIdx.x * 128 + p;

    const float2 uvp = reinterpret_cast<const float2*>(uv)[pix];
    const int    f   = quad[pix];

    int u0 = min(max((int)floorf(uvp.x), 0), NX - 2);
    int v0 = min(max((int)floorf(uvp.y), 0), NX - 2);
    const float du = uvp.x - (float)u0;
    const float dv = uvp.y - (float)v0;

    const __half* base = g_xt + ((size_t)((f * NX + v0) * NX + u0)) * BC + hg * 8;
    const uint4 a00 = *reinterpret_cast<const uint4*>(base);
    const uint4 a01 = *reinterpret_cast<const uint4*>(base + BC);
    const uint4 a10 = *reinterpret_cast<const uint4*>(base + BC * NX);
    const uint4 a11 = *reinterpret_cast<const uint4*>(base + BC * NX + BC);

    const float w00 = (1.0f - du) * (1.0f - dv);
    const float w01 = du * (1.0f - dv);
    const float w10 = (1.0f - du) * dv;
    const float w11 = du * dv;

    float r[8];
#pragma unroll
    for (int j = 0; j < 8; j++) r[j] = 0.0f;
    acc8(r, a00, w00);
    acc8(r, a01, w01);
    acc8(r, a10, w10);
    acc8(r, a11, w11);

    // direct coalesced stores: 16 lanes of same hg -> 16 consecutive pixels
    float* o = out + (size_t)(hg * 8) * HW + pix;
#pragma unroll
    for (int k = 0; k < 8; k++)
        o[(size_t)k * HW] = r[k];
}

extern "C" void kernel_launch(void* const* d_in, const int* in_sizes, int n_in,
                              void* d_out, int out_size) {
    const float* x    = (const float*)d_in[0];   // [2,8,80,128,128] fp32
    const int*   quad = (const int*)  d_in[1];   // [512,1024] int32
    const float* uv   = (const float*)d_in[2];   // [512,1024,2] fp32
    float*       out  = (float*)d_out;           // [2,8,512,1024] fp32

    transpose_kernel<<<M / 1024, 256>>>(x);           // 1280 blocks
    sample_kernel<<<HW / 128, 256>>>(quad, uv, out);  // 4096 blocks
}

// round 5
// speedup vs baseline: 1.0444x; 1.0444x over previous
#include <cuda_runtime.h>
#include <cuda_fp16.h>

// Problem constants
#define FX 80
#define NX 128
#define HH 512
#define WW 1024
#define BC 16                 // B*C fused channel count
#define M  (FX * NX * NX)     // 1310720 texels per channel
#define HW (HH * WW)          // 524288 pixels

// Scratch: x transposed + converted to fp16, layout [M][16] halfs (32B/texel).
__device__ __align__(128) __half g_xt[(size_t)M * BC];

__device__ __forceinline__ unsigned int h2u(__half2 h) {
    return *reinterpret_cast<unsigned int*>(&h);
}

// ---------------------------------------------------------------------------
// Pass 1: fused transpose+convert, register-only (R3 version — measured 20.1us,
// at the streaming roof). Warp does 16 coalesced scalar loads (one per
// channel); lane t then holds texel (m0+t)'s 16 channels in registers ->
// convert to 8 half2, write 32B via 2 STG.128. MLP=16, no smem, no barriers.
// ---------------------------------------------------------------------------
__global__ void __launch_bounds__(256) transpose_kernel(const float* __restrict__ x) {
    const int m = blockIdx.x * 256 + threadIdx.x;   // one texel per thread

    float v[16];
#pragma unroll
    for (int c = 0; c < 16; c++)
        v[c] = __ldg(x + (size_t)c * M + m);        // 16 independent coalesced LDG.32

    unsigned int w[8];
#pragma unroll
    for (int j = 0; j < 8; j++)
        w[j] = h2u(__floats2half2_rn(v[2 * j], v[2 * j + 1]));

    uint4* dst = reinterpret_cast<uint4*>(g_xt + (size_t)m * BC);
    dst[0] = make_uint4(w[0], w[1], w[2], w[3]);
    dst[1] = make_uint4(w[4], w[5], w[6], w[7]);
}

// accumulate 4 fp16 channels (one uint2) into fp32 accumulators with weight w
__device__ __forceinline__ void acc4(float* r, const uint2& a, float w) {
    const __half2* h = reinterpret_cast<const __half2*>(&a);
#pragma unroll
    for (int j = 0; j < 2; j++) {
        float2 f = __half22float2(h[j]);
        r[2 * j]     = fmaf(f.x, w, r[2 * j]);
        r[2 * j + 1] = fmaf(f.y, w, r[2 * j + 1]);
    }
}

// ---------------------------------------------------------------------------
// Pass 2: bilinear gather, 4 threads per pixel (max warp-level parallelism).
// Block = 256 threads = 64 pixels x 4 quarter-groups. Each thread: 4
// independent LDG.64 (8B = 4 fp16 channels per corner). Direct stores: per
// warp per plane, 8 consecutive pixels -> full-sector 32B segments.
// ---------------------------------------------------------------------------
__global__ void __launch_bounds__(256) sample_kernel(const int*   __restrict__ quad,
                                                     const float* __restrict__ uv,
                                                     float*       __restrict__ out) {
    const int t   = threadIdx.x;
    const int p   = t >> 2;            // pixel-in-tile 0..63
    const int qg  = t & 3;             // quarter-group: channels qg*4 .. qg*4+3
    const int pix = blockIdx.x * 64 + p;

    const float2 uvp = reinterpret_cast<const float2*>(uv)[pix];
    const int    f   = quad[pix];

    int u0 = min(max((int)floorf(uvp.x), 0), NX - 2);
    int v0 = min(max((int)floorf(uvp.y), 0), NX - 2);
    const float du = uvp.x - (float)u0;
    const float dv = uvp.y - (float)v0;

    const __half* base = g_xt + ((size_t)((f * NX + v0) * NX + u0)) * BC + qg * 4;
    const uint2 a00 = *reinterpret_cast<const uint2*>(base);
    const uint2 a01 = *reinterpret_cast<const uint2*>(base + BC);
    const uint2 a10 = *reinterpret_cast<const uint2*>(base + BC * NX);
    const uint2 a11 = *reinterpret_cast<const uint2*>(base + BC * NX + BC);

    const float w00 = (1.0f - du) * (1.0f - dv);
    const float w01 = du * (1.0f - dv);
    const float w10 = (1.0f - du) * dv;
    const float w11 = du * dv;

    float r[4];
#pragma unroll
    for (int j = 0; j < 4; j++) r[j] = 0.0f;
    acc4(r, a00, w00);
    acc4(r, a01, w01);
    acc4(r, a10, w10);
    acc4(r, a11, w11);

    // direct stores: 8 lanes of same qg -> 8 consecutive pixels (32B segments)
    float* o = out + (size_t)(qg * 4) * HW + pix;
#pragma unroll
    for (int k = 0; k < 4; k++)
        o[(size_t)k * HW] = r[k];
}

extern "C" void kernel_launch(void* const* d_in, const int* in_sizes, int n_in,
                              void* d_out, int out_size) {
    const float* x    = (const float*)d_in[0];   // [2,8,80,128,128] fp32
    const int*   quad = (const int*)  d_in[1];   // [512,1024] int32
    const float* uv   = (const float*)d_in[2];   // [512,1024,2] fp32
    float*       out  = (float*)d_out;           // [2,8,512,1024] fp32

    transpose_kernel<<<M / 256, 256>>>(x);           // 5120 blocks
    sample_kernel<<<HW / 64, 256>>>(quad, uv, out);  // 8192 blocks
}

// round 6
// speedup vs baseline: 1.0452x; 1.0008x over previous
#include <cuda_runtime.h>
#include <cuda_fp16.h>

// Problem constants
#define FX 80
#define NX 128
#define HH 512
#define WW 1024
#define BC 16                 // B*C fused channel count
#define M  (FX * NX * NX)     // 1310720 texels per channel
#define HW (HH * WW)          // 524288 pixels

// Scratch: x transposed + converted to fp16, layout [M][16] halfs (32B/texel).
__device__ __align__(128) __half g_xt[(size_t)M * BC];

__device__ __forceinline__ unsigned int h2u(__half2 h) {
    return *reinterpret_cast<unsigned int*>(&h);
}

// ---------------------------------------------------------------------------
// Pass 1: fused transpose+convert, register-only (R3 version, measured ~20us,
// at the streaming roof). Warp does 16 coalesced scalar loads (one per
// channel); lane t then holds texel (m0+t)'s 16 channels in registers ->
// convert to 8 half2, write 32B via 2 STG.128. MLP=16, no smem, no barriers.
// ---------------------------------------------------------------------------
__global__ void __launch_bounds__(256) transpose_kernel(const float* __restrict__ x) {
    const int m = blockIdx.x * 256 + threadIdx.x;   // one texel per thread

    float v[16];
#pragma unroll
    for (int c = 0; c < 16; c++)
        v[c] = __ldg(x + (size_t)c * M + m);        // 16 independent coalesced LDG.32

    unsigned int w[8];
#pragma unroll
    for (int j = 0; j < 8; j++)
        w[j] = h2u(__floats2half2_rn(v[2 * j], v[2 * j + 1]));

    uint4* dst = reinterpret_cast<uint4*>(g_xt + (size_t)m * BC);
    dst[0] = make_uint4(w[0], w[1], w[2], w[3]);
    dst[1] = make_uint4(w[4], w[5], w[6], w[7]);
}

// ---------------------------------------------------------------------------
// Pass 2: bilinear gather, 4 lanes per pixel, ROW-contiguous loads.
// Lane q (0..3) of a pixel loads chunk q of each 64B row:
//   q=0: (u0,   ch0-7)   q=1: (u0,   ch8-15)
//   q=2: (u0+1, ch0-7)   q=3: (u0+1, ch8-15)
// One LDG.128 covers a pixel's ENTIRE 64B row -> ~1.25 lines/pixel/instr,
// 2 instrs total => ~2.5 L1tex wavefronts per pixel (vs 4 before).
// Per-thread: r = row0_chunk * w_row0 + row1_chunk * w_row1 (fp32), then one
// shfl_xor(2) butterfly sums the u0/u0+1 halves. Lane q stores 4 channels;
// 8 same-q lanes per warp -> 8 consecutive pixels = full 32B store sectors.
// ---------------------------------------------------------------------------
__global__ void __launch_bounds__(256) sample_kernel(const int*   __restrict__ quad,
                                                     const float* __restrict__ uv,
                                                     float*       __restrict__ out) {
    const int t   = threadIdx.x;
    const int p   = t >> 2;            // pixel-in-tile 0..63
    const int q   = t & 3;             // lane role within pixel
    const int pix = blockIdx.x * 64 + p;

    const float2 uvp = reinterpret_cast<const float2*>(uv)[pix];
    const int    f   = quad[pix];

    int u0 = min(max((int)floorf(uvp.x), 0), NX - 2);
    int v0 = min(max((int)floorf(uvp.y), 0), NX - 2);
    const float du = uvp.x - (float)u0;
    const float dv = uvp.y - (float)v0;

    // this lane's u-side weight factor
    const float su = (q >= 2) ? du : (1.0f - du);
    const float w0 = su * (1.0f - dv);   // row v0
    const float w1 = su * dv;            // row v0+1

    const __half* row0 = g_xt + ((size_t)((f * NX + v0) * NX + u0)) * BC + q * 8;
    const uint4 a0 = *reinterpret_cast<const uint4*>(row0);            // 16B of row v0
    const uint4 a1 = *reinterpret_cast<const uint4*>(row0 + BC * NX);  // 16B of row v0+1

    // r[k] = a0[k]*w0 + a1[k]*w1  (fp32)
    float r[8];
    {
        const __half2* h0 = reinterpret_cast<const __half2*>(&a0);
        const __half2* h1 = reinterpret_cast<const __half2*>(&a1);
#pragma unroll
        for (int j = 0; j < 4; j++) {
            float2 f0 = __half22float2(h0[j]);
            float2 f1 = __half22float2(h1[j]);
            r[2 * j]     = fmaf(f0.x, w0, f1.x * w1);
            r[2 * j + 1] = fmaf(f0.y, w0, f1.y * w1);
        }
    }

    // sum u0-half (lanes q and q^2 share the same channel set)
#pragma unroll
    for (int k = 0; k < 8; k++)
        r[k] += __shfl_xor_sync(0xffffffffu, r[k], 2);

    // lane q stores 4 channels: c0 = (q&1)*8 + (q>>1)*4
    const int c0 = (q & 1) * 8 + (q >> 1) * 4;
    float* o = out + (size_t)c0 * HW + pix;
#pragma unroll
    for (int k = 0; k < 4; k++)
        o[(size_t)k * HW] = r[((q & 1) ? 8 : 0) ? 0 : ((q >> 1) * 4 + k)];  // placeholder fixed below

    // NOTE: r holds this lane's 8 channel values for channels (q&1)*8 .. +7;
    // the 4 stored are the (q>>1) half of those:
}

// The store indexing above is subtle; use a clean dedicated kernel instead.
__global__ void __launch_bounds__(256) sample_kernel2(const int*   __restrict__ quad,
                                                      const float* __restrict__ uv,
                                                      float*       __restrict__ out) {
    const int t   = threadIdx.x;
    const int p   = t >> 2;
    const int q   = t & 3;
    const int pix = blockIdx.x * 64 + p;

    const float2 uvp = reinterpret_cast<const float2*>(uv)[pix];
    const int    f   = quad[pix];

    int u0 = min(max((int)floorf(uvp.x), 0), NX - 2);
    int v0 = min(max((int)floorf(uvp.y), 0), NX - 2);
    const float du = uvp.x - (float)u0;
    const float dv = uvp.y - (float)v0;

    const float su = (q >= 2) ? du : (1.0f - du);
    const float w0 = su * (1.0f - dv);
    const float w1 = su * dv;

    const __half* row0 = g_xt + ((size_t)((f * NX + v0) * NX + u0)) * BC + q * 8;
    const uint4 a0 = *reinterpret_cast<const uint4*>(row0);
    const uint4 a1 = *reinterpret_cast<const uint4*>(row0 + BC * NX);

    float r[8];
    const __half2* h0 = reinterpret_cast<const __half2*>(&a0);
    const __half2* h1 = reinterpret_cast<const __half2*>(&a1);
#pragma unroll
    for (int j = 0; j < 4; j++) {
        float2 f0 = __half22float2(h0[j]);
        float2 f1 = __half22float2(h1[j]);
        r[2 * j]     = fmaf(f0.x, w0, f1.x * w1);
        r[2 * j + 1] = fmaf(f0.y, w0, f1.y * w1);
    }

#pragma unroll
    for (int k = 0; k < 8; k++)
        r[k] += __shfl_xor_sync(0xffffffffu, r[k], 2);

    // lane's channel block: chBase = (q&1)*8 (its 8 r-values are chBase..chBase+7).
    // Store the (q>>1)-th group of 4 to avoid duplication with lane q^2.
    const int sub = (q >> 1) * 4;                 // 0 or 4 within the lane's 8
    const int c0  = (q & 1) * 8 + sub;            // global channel of r[sub]
    float* o = out + (size_t)c0 * HW + pix;
#pragma unroll
    for (int k = 0; k < 4; k++)
        o[(size_t)k * HW] = r[sub + k];
}

extern "C" void kernel_launch(void* const* d_in, const int* in_sizes, int n_in,
                              void* d_out, int out_size) {
    const float* x    = (const float*)d_in[0];   // [2,8,80,128,128] fp32
    const int*   quad = (const int*)  d_in[1];   // [512,1024] int32
    const float* uv   = (const float*)d_in[2];   // [512,1024,2] fp32
    float*       out  = (float*)d_out;           // [2,8,512,1024] fp32

    transpose_kernel<<<M / 256, 256>>>(x);            // 5120 blocks
    sample_kernel2<<<HW / 64, 256>>>(quad, uv, out);  // 8192 blocks
}